// round 5
// baseline (speedup 1.0000x reference)
#include <cuda_runtime.h>
#include <cuda_bf16.h>
#include <cstdint>

// Problem constants
#define BB   2
#define SS   2048
#define DIM  2048
#define NH   16
#define DH   128
#define LKV  512
#define LQ   1024
#define MR   (BB*SS)    // 4096
#define HD   (NH*DH)    // 2048

// Static scratch
__device__ float g_cq [MR*(size_t)LQ];
__device__ float g_ckv[MR*(size_t)LKV];
__device__ float g_qa [MR*(size_t)HD];
__device__ float g_qr [MR*(size_t)HD];
__device__ float g_ka [MR*(size_t)HD];
__device__ float g_kr [MR*(size_t)HD];
__device__ float g_v  [MR*(size_t)HD];
__device__ float g_vt [(size_t)BB*NH*DH*SS];   // V transposed per (b,h): [d][s]
__device__ float g_att[MR*(size_t)HD];
__device__ float g_sc [(size_t)BB*NH*SS*SS];   // 512 MB score scratch

// ---------------------------------------------------------------------------
// Helpers
// ---------------------------------------------------------------------------
__device__ __forceinline__ uint32_t smem_u32(const void* p) {
    uint32_t a;
    asm("{ .reg .u64 t; cvta.to.shared.u64 t, %1; cvt.u32.u64 %0, t; }" : "=r"(a) : "l"(p));
    return a;
}

__device__ __forceinline__ void ldm_x4(uint32_t addr, uint32_t r[4]) {
    asm volatile("ldmatrix.sync.aligned.m8n8.x4.shared.b16 {%0,%1,%2,%3}, [%4];"
                 : "=r"(r[0]), "=r"(r[1]), "=r"(r[2]), "=r"(r[3]) : "r"(addr));
}

__device__ __forceinline__ void mma16816(float c[4], const uint32_t a[4],
                                         uint32_t b0, uint32_t b1) {
    asm volatile(
        "mma.sync.aligned.m16n8k16.row.col.f32.bf16.bf16.f32 "
        "{%0,%1,%2,%3}, {%4,%5,%6,%7}, {%8,%9}, {%0,%1,%2,%3};"
        : "+f"(c[0]), "+f"(c[1]), "+f"(c[2]), "+f"(c[3])
        : "r"(a[0]), "r"(a[1]), "r"(a[2]), "r"(a[3]), "r"(b0), "r"(b1));
}

__device__ __forceinline__ uint32_t packbf(float a, float b) {
    uint32_t r;
    asm("cvt.rn.satfinite.bf16x2.f32 %0, %1, %2;" : "=r"(r) : "f"(b), "f"(a));
    return r;
}
__device__ __forceinline__ float lo_of(uint32_t h) { return __uint_as_float(h << 16); }
__device__ __forceinline__ float hi_of(uint32_t h) { return __uint_as_float(h & 0xFFFF0000u); }

__device__ __forceinline__ void sts_v4(uint32_t addr, uint4 v) {
    asm volatile("st.shared.v4.b32 [%0], {%1,%2,%3,%4};"
                 :: "r"(addr), "r"(v.x), "r"(v.y), "r"(v.z), "r"(v.w) : "memory");
}

__device__ __forceinline__ uint4 split_hi(float4 a, float4 b) {
    uint4 h;
    h.x = packbf(a.x, a.y); h.y = packbf(a.z, a.w);
    h.z = packbf(b.x, b.y); h.w = packbf(b.z, b.w);
    return h;
}
__device__ __forceinline__ uint4 split_lo(float4 a, float4 b, uint4 h) {
    uint4 l;
    l.x = packbf(a.x - lo_of(h.x), a.y - hi_of(h.x));
    l.y = packbf(a.z - lo_of(h.y), a.w - hi_of(h.y));
    l.z = packbf(b.x - lo_of(h.z), b.y - hi_of(h.z));
    l.w = packbf(b.z - lo_of(h.w), b.w - hi_of(h.w));
    return l;
}

#define PITCH 80

// ---------------------------------------------------------------------------
// Warp-MMA GEMM: C = alpha * A * B^T [+ bias]
//   CTA tile 128 x BN (BN = 128 or 256), 512 threads, warp tile 32 x BN/4.
//   A [M,K] rm, B [N,K] rm. DUAL: accumulate A2*B2^T too. Batched via grid.z.
//   K multiple of 32. bf16 hi/lo split (3-product) for fp32-level accuracy.
// ---------------------------------------------------------------------------
template<int BN, bool BIAS, bool DUAL>
__global__ __launch_bounds__(512)
void tgemm(int K,
           const float* __restrict__ A, int lda, long long sAb, long long sAh,
           const float* __restrict__ Bm, int ldb, long long sBb, long long sBh,
           const float* __restrict__ A2, const float* __restrict__ B2,
           float* __restrict__ C, int ldc, long long sCb, long long sCh,
           const float* __restrict__ bias, float alpha, int Hdiv)
{
    constexpr int NT = BN / 32;        // n-subtiles (8-wide) per warp: 8 or 4
    constexpr int NP = BN / 64;        // 16-row B ldmatrix groups per warp: 4 or 2
    constexpr int OF_ALO = 10240;
    constexpr int OF_BHI = 20480;
    constexpr int OF_BLO = 20480 + BN * PITCH;
    constexpr int STAGE  = 20480 + 2 * BN * PITCH;

    extern __shared__ __align__(128) char smc[];
    const uint32_t smb = smem_u32(smc);
    const int tid  = threadIdx.x;
    const int lane = tid & 31;
    const int wid  = tid >> 5;
    const int wm   = (wid & 3) * 32;
    const int wn   = (wid >> 2) * (BN / 4);

    int z = blockIdx.z;
    int zb = z / Hdiv, zh = z - zb * Hdiv;
    A  += zb * sAb + zh * sAh;
    Bm += zb * sBb + zh * sBh;
    if (DUAL) { A2 += zb * sAb + zh * sAh; B2 += zb * sBb + zh * sBh; }
    C  += zb * sCb + zh * sCh;

    const int arow = tid >> 2;          // 0..127
    const int ako  = (tid & 3) * 8;
    const long long aoff  = (long long)(blockIdx.y * 128 + arow) * lda;
    const long long boff  = (long long)(blockIdx.x * BN + arow) * ldb;
    const long long boff2 = boff + 128LL * ldb;   // only BN=256

    float acc[2][NT][4];
#pragma unroll
    for (int i = 0; i < 2; i++)
#pragma unroll
        for (int j = 0; j < NT; j++)
#pragma unroll
            for (int k = 0; k < 4; k++) acc[i][j][k] = 0.f;

    const int nch   = K >> 5;
    const int total = DUAL ? nch * 2 : nch;

    float4 ra0, ra1, rb0, rb1, rc0, rc1;

    auto LDG = [&](int c) {
        const float* Ap = A; const float* Bp = Bm; int cc = c;
        if (DUAL && c >= nch) { Ap = A2; Bp = B2; cc = c - nch; }
        const float* pa = Ap + aoff + cc * 32 + ako;
        const float* pb = Bp + boff + cc * 32 + ako;
        ra0 = *(const float4*)pa; ra1 = *(const float4*)(pa + 4);
        rb0 = *(const float4*)pb; rb1 = *(const float4*)(pb + 4);
        if (BN == 256) {
            const float* pc = Bp + boff2 + cc * 32 + ako;
            rc0 = *(const float4*)pc; rc1 = *(const float4*)(pc + 4);
        }
    };

    auto STS = [&](int s) {
        const uint32_t base = smb + s * STAGE + arow * PITCH + ako * 2;
        uint4 h = split_hi(ra0, ra1);
        sts_v4(base, h);
        sts_v4(base + OF_ALO, split_lo(ra0, ra1, h));
        h = split_hi(rb0, rb1);
        sts_v4(base + OF_BHI, h);
        sts_v4(base + OF_BLO, split_lo(rb0, rb1, h));
        if (BN == 256) {
            h = split_hi(rc0, rc1);
            sts_v4(base + OF_BHI + 128 * PITCH, h);
            sts_v4(base + OF_BLO + 128 * PITCH, split_lo(rc0, rc1, h));
        }
    };

    auto COMPUTE = [&](int s) {
        const uint32_t sa = smb + s * STAGE;
#pragma unroll
        for (int ks = 0; ks < 2; ++ks) {
            const uint32_t colb = ks * 32;
            uint32_t ahi[2][4], alo[2][4];
#pragma unroll
            for (int mt = 0; mt < 2; ++mt) {
                uint32_t addr = sa +
                    (wm + mt * 16 + (lane & 15)) * PITCH + colb + (lane >> 4) * 16;
                ldm_x4(addr, ahi[mt]);
                ldm_x4(addr + OF_ALO, alo[mt]);
            }
#pragma unroll
            for (int np = 0; np < NP; ++np) {
                uint32_t bhi[4], blo[4];
                uint32_t addr = sa + OF_BHI +
                    (wn + np * 16 + (lane & 7) + ((lane >> 4) << 3)) * PITCH +
                    colb + ((lane >> 3) & 1) * 16;
                ldm_x4(addr, bhi);
                ldm_x4(addr + (OF_BLO - OF_BHI), blo);
#pragma unroll
                for (int mt = 0; mt < 2; ++mt)
#pragma unroll
                    for (int ntl = 0; ntl < 2; ++ntl) {
                        float* a = acc[mt][np * 2 + ntl];
                        mma16816(a, ahi[mt], bhi[2 * ntl], bhi[2 * ntl + 1]);
                        mma16816(a, ahi[mt], blo[2 * ntl], blo[2 * ntl + 1]);
                        mma16816(a, alo[mt], bhi[2 * ntl], bhi[2 * ntl + 1]);
                    }
            }
        }
    };

    LDG(0);
    STS(0);
    __syncthreads();
    for (int c = 0; c < total; ++c) {
        if (c + 1 < total) LDG(c + 1);
        COMPUTE(c & 1);
        if (c + 1 < total) STS((c + 1) & 1);
        __syncthreads();
    }

    const int g = lane >> 2, t = lane & 3;
#pragma unroll
    for (int mt = 0; mt < 2; ++mt) {
        const int r0 = blockIdx.y * 128 + wm + mt * 16 + g;
#pragma unroll
        for (int nt = 0; nt < NT; ++nt) {
            const int col = blockIdx.x * BN + wn + nt * 8 + t * 2;
            float b0 = 0.f, b1 = 0.f;
            if (BIAS) { b0 = bias[col]; b1 = bias[col + 1]; }
            float2 v0, v1;
            v0.x = alpha * acc[mt][nt][0] + b0;
            v0.y = alpha * acc[mt][nt][1] + b1;
            v1.x = alpha * acc[mt][nt][2] + b0;
            v1.y = alpha * acc[mt][nt][3] + b1;
            *(float2*)&C[(long long)r0 * ldc + col] = v0;
            *(float2*)&C[(long long)(r0 + 8) * ldc + col] = v1;
        }
    }
}

// ---------------------------------------------------------------------------
// Transpose V: vt[(b*NH+h)*DH + d][s] = v[(b*SS+s)*HD + h*DH + d]
// ---------------------------------------------------------------------------
__global__ void transpose_v(const float* __restrict__ v, float* __restrict__ vt)
{
    __shared__ float t[32][33];
    int z = blockIdx.z;
    int b = z / NH, h = z - b * NH;
    int s0 = blockIdx.y * 32, d0 = blockIdx.x * 32;
    int x = threadIdx.x, y = threadIdx.y;
#pragma unroll
    for (int i = 0; i < 32; i += 8)
        t[y + i][x] = v[((long long)(b * SS + s0 + y + i)) * HD + h * DH + d0 + x];
    __syncthreads();
#pragma unroll
    for (int i = 0; i < 32; i += 8)
        vt[((long long)(z * DH + d0 + y + i)) * SS + s0 + x] = t[x][y + i];
}

// ---------------------------------------------------------------------------
// RoPE in-place on a [B*S, H*DH] buffer.
// ---------------------------------------------------------------------------
__global__ void rope_kernel(float* __restrict__ t,
                            const float* __restrict__ fc,
                            const float* __restrict__ fs)
{
    long long idx = (long long)blockIdx.x * blockDim.x + threadIdx.x;
    const long long total = (long long)MR * NH * (DH / 2);
    if (idx >= total) return;
    int i = (int)(idx & 63);
    long long t2 = idx >> 6;
    int h = (int)(t2 % NH);
    long long row = t2 / NH;
    int s = (int)(row % SS);
    float c  = fc[s * 64 + i];
    float sn = fs[s * 64 + i];
    float* p = t + row * HD + h * DH + 2 * i;
    float e = p[0], o = p[1];
    p[0] = e * c - o * sn;
    p[1] = e * sn + o * c;
}

// ---------------------------------------------------------------------------
// Register-resident row softmax: row length 2048, 256 threads, 8 vals/thread.
// One global read + one global write.
// ---------------------------------------------------------------------------
__global__ __launch_bounds__(256) void softmax_rows(float* __restrict__ S)
{
    float* p = S + (long long)blockIdx.x * SS;
    const int t = threadIdx.x;
    __shared__ float red[8];

    float v[8];
#pragma unroll
    for (int j = 0; j < 8; ++j) v[j] = p[t + 256 * j];

    float m = v[0];
#pragma unroll
    for (int j = 1; j < 8; ++j) m = fmaxf(m, v[j]);
#pragma unroll
    for (int o = 16; o > 0; o >>= 1) m = fmaxf(m, __shfl_xor_sync(~0u, m, o));
    if ((t & 31) == 0) red[t >> 5] = m;
    __syncthreads();
    if (t < 32) {
        float mm = red[t & 7];
#pragma unroll
        for (int o = 4; o > 0; o >>= 1) mm = fmaxf(mm, __shfl_xor_sync(~0u, mm, o));
        if (t == 0) red[0] = mm;
    }
    __syncthreads();
    m = red[0];
    __syncthreads();

    float sum = 0.f;
#pragma unroll
    for (int j = 0; j < 8; ++j) { v[j] = __expf(v[j] - m); sum += v[j]; }
#pragma unroll
    for (int o = 16; o > 0; o >>= 1) sum += __shfl_xor_sync(~0u, sum, o);
    if ((t & 31) == 0) red[t >> 5] = sum;
    __syncthreads();
    if (t < 32) {
        float ss = red[t & 7];
#pragma unroll
        for (int o = 4; o > 0; o >>= 1) ss += __shfl_xor_sync(~0u, ss, o);
        if (t == 0) red[0] = ss;
    }
    __syncthreads();
    const float inv = 1.0f / red[0];
#pragma unroll
    for (int j = 0; j < 8; ++j) p[t + 256 * j] = v[j] * inv;
}

// ---------------------------------------------------------------------------

#define SMEM_256 (2*(20480 + 2*256*PITCH))   // 122880
#define SMEM_128 (2*(20480 + 2*128*PITCH))   // 81920

extern "C" void kernel_launch(void* const* d_in, const int* in_sizes, int n_in,
                              void* d_out, int out_size)
{
    const float* x    = (const float*)d_in[0];
    const float* fc   = (const float*)d_in[1];
    const float* fs   = (const float*)d_in[2];
    const float* w_lq = (const float*)d_in[3];
    const float* w_lkv= (const float*)d_in[4];
    const float* w_q  = (const float*)d_in[5];
    const float* w_k  = (const float*)d_in[6];
    const float* w_v  = (const float*)d_in[7];
    const float* w_qr = (const float*)d_in[8];
    const float* b_qr = (const float*)d_in[9];
    const float* w_kr = (const float*)d_in[10];
    const float* b_kr = (const float*)d_in[11];
    const float* w_o  = (const float*)d_in[12];
    const float* b_o  = (const float*)d_in[13];
    float* out = (float*)d_out;

    float *cq, *ckv, *qa, *qr, *ka, *kr, *vv, *vt, *att, *sc;
    cudaGetSymbolAddress((void**)&cq,  g_cq);
    cudaGetSymbolAddress((void**)&ckv, g_ckv);
    cudaGetSymbolAddress((void**)&qa,  g_qa);
    cudaGetSymbolAddress((void**)&qr,  g_qr);
    cudaGetSymbolAddress((void**)&ka,  g_ka);
    cudaGetSymbolAddress((void**)&kr,  g_kr);
    cudaGetSymbolAddress((void**)&vv,  g_v);
    cudaGetSymbolAddress((void**)&vt,  g_vt);
    cudaGetSymbolAddress((void**)&att, g_att);
    cudaGetSymbolAddress((void**)&sc,  g_sc);

    static bool attr_done = false;
    if (!attr_done) {
        cudaFuncSetAttribute(tgemm<256, false, false>, cudaFuncAttributeMaxDynamicSharedMemorySize, SMEM_256);
        cudaFuncSetAttribute(tgemm<256, true,  false>, cudaFuncAttributeMaxDynamicSharedMemorySize, SMEM_256);
        cudaFuncSetAttribute(tgemm<256, false, true >, cudaFuncAttributeMaxDynamicSharedMemorySize, SMEM_256);
        cudaFuncSetAttribute(tgemm<128, false, false>, cudaFuncAttributeMaxDynamicSharedMemorySize, SMEM_128);
        attr_done = true;
    }

    const float scale = 0.08838834764831845f; // 1/sqrt(128)

    // --- projections ---
    tgemm<256, false, false><<<dim3(LQ/256, MR/128, 1), 512, SMEM_256>>>(
        DIM, x, DIM, 0, 0, w_lq, DIM, 0, 0, nullptr, nullptr,
        cq, LQ, 0, 0, nullptr, 1.f, 1);
    tgemm<256, false, false><<<dim3(LKV/256, MR/128, 1), 512, SMEM_256>>>(
        DIM, x, DIM, 0, 0, w_lkv, DIM, 0, 0, nullptr, nullptr,
        ckv, LKV, 0, 0, nullptr, 1.f, 1);
    tgemm<256, false, false><<<dim3(HD/256, MR/128, 1), 512, SMEM_256>>>(
        LQ, cq, LQ, 0, 0, w_q, LQ, 0, 0, nullptr, nullptr,
        qa, HD, 0, 0, nullptr, 1.f, 1);
    tgemm<256, true, false><<<dim3(HD/256, MR/128, 1), 512, SMEM_256>>>(
        LQ, cq, LQ, 0, 0, w_qr, LQ, 0, 0, nullptr, nullptr,
        qr, HD, 0, 0, b_qr, 1.f, 1);
    tgemm<256, false, false><<<dim3(HD/256, MR/128, 1), 512, SMEM_256>>>(
        LKV, ckv, LKV, 0, 0, w_k, LKV, 0, 0, nullptr, nullptr,
        ka, HD, 0, 0, nullptr, 1.f, 1);
    tgemm<256, true, false><<<dim3(HD/256, MR/128, 1), 512, SMEM_256>>>(
        DIM, x, DIM, 0, 0, w_kr, DIM, 0, 0, nullptr, nullptr,
        kr, HD, 0, 0, b_kr, 1.f, 1);
    tgemm<256, false, false><<<dim3(HD/256, MR/128, 1), 512, SMEM_256>>>(
        LKV, ckv, LKV, 0, 0, w_v, LKV, 0, 0, nullptr, nullptr,
        vv, HD, 0, 0, nullptr, 1.f, 1);

    // --- RoPE on qr, kr ---
    {
        long long pairs = (long long)MR * NH * (DH / 2);
        int blocks = (int)((pairs + 255) / 256);
        rope_kernel<<<blocks, 256>>>(qr, fc, fs);
        rope_kernel<<<blocks, 256>>>(kr, fc, fs);
    }

    // --- transpose V ---
    transpose_v<<<dim3(DH/32, SS/32, BB*NH), dim3(32, 8)>>>(vv, vt);

    // --- scores: sc[z] = (qa.ka^T + qr.kr^T) * scale ---
    {
        long long sQb = (long long)SS * HD;
        long long sQh = DH;
        long long sSb = (long long)NH * SS * SS;
        long long sSh = (long long)SS * SS;
        tgemm<256, false, true><<<dim3(SS/256, SS/128, BB*NH), 512, SMEM_256>>>(
            DH, qa, HD, sQb, sQh, ka, HD, sQb, sQh, qr, kr,
            sc, SS, sSb, sSh, nullptr, scale, NH);
    }

    // --- softmax ---
    softmax_rows<<<BB * NH * SS, 256>>>(sc);

    // --- PV: att = P @ vt^T ---
    {
        long long sSb = (long long)NH * SS * SS;
        long long sSh = (long long)SS * SS;
        long long sVtb = (long long)NH * DH * SS;
        long long sVth = (long long)DH * SS;
        long long sCb = (long long)SS * HD;
        long long sCh = DH;
        tgemm<128, false, false><<<dim3(DH/128, SS/128, BB*NH), 512, SMEM_128>>>(
            SS, sc, SS, sSb, sSh, vt, SS, sVtb, sVth, nullptr, nullptr,
            att, HD, sCb, sCh, nullptr, 1.f, NH);
    }

    // --- out = att @ w_o^T + b_o ---
    tgemm<256, true, false><<<dim3(DIM/256, MR/128, 1), 512, SMEM_256>>>(
        HD, att, HD, 0, 0, w_o, HD, 0, 0, nullptr, nullptr,
        out, DIM, 0, 0, b_o, 1.f, 1);

    (void)in_sizes; (void)n_in; (void)out_size;
}

// round 6
// speedup vs baseline: 1.6362x; 1.6362x over previous
#include <cuda_runtime.h>
#include <cuda_bf16.h>
#include <cstdint>

// Problem constants
#define BB   2
#define SS   2048
#define DIM  2048
#define NH   16
#define DH   128
#define LKV  512
#define LQ   1024
#define MR   (BB*SS)    // 4096
#define HD   (NH*DH)    // 2048

// Static scratch
__device__ float g_cq [MR*(size_t)LQ];
__device__ float g_ckv[MR*(size_t)LKV];
__device__ float g_qa [MR*(size_t)HD];
__device__ float g_qr [MR*(size_t)HD];
__device__ float g_ka [MR*(size_t)HD];
__device__ float g_kr [MR*(size_t)HD];
__device__ float g_v  [MR*(size_t)HD];
__device__ float g_vt [(size_t)BB*NH*DH*SS];   // V transposed per (b,h): [d][s]
__device__ float g_att[MR*(size_t)HD];
__device__ float g_sc [(size_t)BB*NH*SS*SS];   // 512 MB score scratch

// ---------------------------------------------------------------------------
// Helpers
// ---------------------------------------------------------------------------
__device__ __forceinline__ uint32_t smem_u32(const void* p) {
    uint32_t a;
    asm("{ .reg .u64 t; cvta.to.shared.u64 t, %1; cvt.u32.u64 %0, t; }" : "=r"(a) : "l"(p));
    return a;
}

__device__ __forceinline__ void ldm_x4(uint32_t addr, uint32_t r[4]) {
    asm volatile("ldmatrix.sync.aligned.m8n8.x4.shared.b16 {%0,%1,%2,%3}, [%4];"
                 : "=r"(r[0]), "=r"(r[1]), "=r"(r[2]), "=r"(r[3]) : "r"(addr));
}

__device__ __forceinline__ void mma16816(float c[4], const uint32_t a[4],
                                         uint32_t b0, uint32_t b1) {
    asm volatile(
        "mma.sync.aligned.m16n8k16.row.col.f32.bf16.bf16.f32 "
        "{%0,%1,%2,%3}, {%4,%5,%6,%7}, {%8,%9}, {%0,%1,%2,%3};"
        : "+f"(c[0]), "+f"(c[1]), "+f"(c[2]), "+f"(c[3])
        : "r"(a[0]), "r"(a[1]), "r"(a[2]), "r"(a[3]), "r"(b0), "r"(b1));
}

// pack two fp32 -> bf16x2 {lower=a, upper=b}
__device__ __forceinline__ uint32_t packbf(float a, float b) {
    uint32_t r;
    asm("cvt.rn.satfinite.bf16x2.f32 %0, %1, %2;" : "=r"(r) : "f"(b), "f"(a));
    return r;
}
__device__ __forceinline__ float lo_of(uint32_t h) { return __uint_as_float(h << 16); }
__device__ __forceinline__ float hi_of(uint32_t h) { return __uint_as_float(h & 0xFFFF0000u); }

__device__ __forceinline__ void sts_v4(uint32_t addr, uint4 v) {
    asm volatile("st.shared.v4.b32 [%0], {%1,%2,%3,%4};"
                 :: "r"(addr), "r"(v.x), "r"(v.y), "r"(v.z), "r"(v.w) : "memory");
}

// SMEM layout: per stage: A_hi, A_lo, B_hi, B_lo tiles of 128 rows x 80B pitch
#define PITCH    80
#define OF_ALO   10240
#define OF_BHI   20480
#define OF_BLO   30720
#define STAGE_SZ 40960
#define SMEMSZ   81920

// ---------------------------------------------------------------------------
// Warp-MMA GEMM: C = alpha * A * B^T [+ bias]
//   A [M,K] row-major (lda), B [N,K] row-major (ldb), C [M,N] (ldc)
//   DUAL: continue accumulating A2 * B2^T (same shapes) before epilogue
//   Batched via grid.z: z -> (zb=z/Hdiv, zh=z%Hdiv), pointer offsets.
//   Grid: (N/128, M/128, Z), block = 512 threads (16 warps, 32x32 warp tiles).
//   K multiple of 32. bf16 hi/lo split, 3-product fp32-accurate emulation.
// ---------------------------------------------------------------------------
template<bool BIAS, bool DUAL>
__global__ __launch_bounds__(512)
void tgemm(int K,
           const float* __restrict__ A, int lda, long long sAb, long long sAh,
           const float* __restrict__ Bm, int ldb, long long sBb, long long sBh,
           const float* __restrict__ A2, const float* __restrict__ B2,
           float* __restrict__ C, int ldc, long long sCb, long long sCh,
           const float* __restrict__ bias, float alpha, int Hdiv)
{
    extern __shared__ __align__(128) char smc[];
    const uint32_t smb = smem_u32(smc);
    const int tid  = threadIdx.x;
    const int lane = tid & 31;
    const int wid  = tid >> 5;
    const int wm   = (wid & 3) * 32;   // warp M offset in 128
    const int wn   = (wid >> 2) * 32;  // warp N offset in 128

    int z = blockIdx.z;
    int zb = z / Hdiv, zh = z - zb * Hdiv;
    A  += zb * sAb + zh * sAh;
    Bm += zb * sBb + zh * sBh;
    if (DUAL) { A2 += zb * sAb + zh * sAh; B2 += zb * sBb + zh * sBh; }
    C  += zb * sCb + zh * sCh;

    // global staging mapping: 512 threads cover 128 rows x 32 k (8 floats each)
    const int arow = tid >> 2;
    const int ako  = (tid & 3) * 8;
    const long long aoff = (long long)(blockIdx.y * 128 + arow) * lda;
    const long long boff = (long long)(blockIdx.x * 128 + arow) * ldb;

    float acc[2][4][4];
#pragma unroll
    for (int i = 0; i < 2; i++)
#pragma unroll
        for (int j = 0; j < 4; j++)
#pragma unroll
            for (int k = 0; k < 4; k++) acc[i][j][k] = 0.f;

    const int nch   = K >> 5;
    const int total = DUAL ? nch * 2 : nch;

    float4 ra0, ra1, rb0, rb1;

    auto LDG = [&](int c) {
        const float* Ap = A; const float* Bp = Bm; int cc = c;
        if (DUAL && c >= nch) { Ap = A2; Bp = B2; cc = c - nch; }
        const float* pa = Ap + aoff + cc * 32 + ako;
        const float* pb = Bp + boff + cc * 32 + ako;
        ra0 = *(const float4*)pa; ra1 = *(const float4*)(pa + 4);
        rb0 = *(const float4*)pb; rb1 = *(const float4*)(pb + 4);
    };

    auto STS = [&](int s) {
        const uint32_t base = smb + s * STAGE_SZ + arow * PITCH + ako * 2;
        // A
        uint4 hi, lo;
        hi.x = packbf(ra0.x, ra0.y); hi.y = packbf(ra0.z, ra0.w);
        hi.z = packbf(ra1.x, ra1.y); hi.w = packbf(ra1.z, ra1.w);
        lo.x = packbf(ra0.x - lo_of(hi.x), ra0.y - hi_of(hi.x));
        lo.y = packbf(ra0.z - lo_of(hi.y), ra0.w - hi_of(hi.y));
        lo.z = packbf(ra1.x - lo_of(hi.z), ra1.y - hi_of(hi.z));
        lo.w = packbf(ra1.z - lo_of(hi.w), ra1.w - hi_of(hi.w));
        sts_v4(base, hi);
        sts_v4(base + OF_ALO, lo);
        // B
        hi.x = packbf(rb0.x, rb0.y); hi.y = packbf(rb0.z, rb0.w);
        hi.z = packbf(rb1.x, rb1.y); hi.w = packbf(rb1.z, rb1.w);
        lo.x = packbf(rb0.x - lo_of(hi.x), rb0.y - hi_of(hi.x));
        lo.y = packbf(rb0.z - lo_of(hi.y), rb0.w - hi_of(hi.y));
        lo.z = packbf(rb1.x - lo_of(hi.z), rb1.y - hi_of(hi.z));
        lo.w = packbf(rb1.z - lo_of(hi.w), rb1.w - hi_of(hi.w));
        sts_v4(base + OF_BHI, hi);
        sts_v4(base + OF_BLO, lo);
    };

    auto COMPUTE = [&](int s) {
        const uint32_t sa = smb + s * STAGE_SZ;
#pragma unroll
        for (int ks = 0; ks < 2; ++ks) {
            const uint32_t colb = ks * 32;
            uint32_t ahi[2][4], alo[2][4], bhi[2][4], blo[2][4];
#pragma unroll
            for (int mt = 0; mt < 2; ++mt) {
                uint32_t addr = sa +
                    (wm + mt * 16 + (lane & 15)) * PITCH + colb + (lane >> 4) * 16;
                ldm_x4(addr, ahi[mt]);
                ldm_x4(addr + OF_ALO, alo[mt]);
            }
#pragma unroll
            for (int np = 0; np < 2; ++np) {
                uint32_t addr = sa + OF_BHI +
                    (wn + np * 16 + (lane & 7) + ((lane >> 4) << 3)) * PITCH +
                    colb + ((lane >> 3) & 1) * 16;
                ldm_x4(addr, bhi[np]);
                ldm_x4(addr + (OF_BLO - OF_BHI), blo[np]);
            }
#pragma unroll
            for (int mt = 0; mt < 2; ++mt)
#pragma unroll
                for (int nt = 0; nt < 4; ++nt) {
                    uint32_t b0h = bhi[nt >> 1][(nt & 1) * 2];
                    uint32_t b1h = bhi[nt >> 1][(nt & 1) * 2 + 1];
                    uint32_t b0l = blo[nt >> 1][(nt & 1) * 2];
                    uint32_t b1l = blo[nt >> 1][(nt & 1) * 2 + 1];
                    mma16816(acc[mt][nt], ahi[mt], b0h, b1h);
                    mma16816(acc[mt][nt], ahi[mt], b0l, b1l);
                    mma16816(acc[mt][nt], alo[mt], b0h, b1h);
                }
        }
    };

    // --- software pipeline: one sync per chunk ---
    LDG(0);
    STS(0);
    __syncthreads();
    for (int c = 0; c < total; ++c) {
        if (c + 1 < total) LDG(c + 1);
        COMPUTE(c & 1);
        if (c + 1 < total) STS((c + 1) & 1);
        __syncthreads();
    }

    // --- epilogue ---
    const int g = lane >> 2, t = lane & 3;
#pragma unroll
    for (int mt = 0; mt < 2; ++mt) {
        const int r0 = blockIdx.y * 128 + wm + mt * 16 + g;
#pragma unroll
        for (int nt = 0; nt < 4; ++nt) {
            const int col = blockIdx.x * 128 + wn + nt * 8 + t * 2;
            float b0 = 0.f, b1 = 0.f;
            if (BIAS) { b0 = bias[col]; b1 = bias[col + 1]; }
            float2 v0, v1;
            v0.x = alpha * acc[mt][nt][0] + b0;
            v0.y = alpha * acc[mt][nt][1] + b1;
            v1.x = alpha * acc[mt][nt][2] + b0;
            v1.y = alpha * acc[mt][nt][3] + b1;
            *(float2*)&C[(long long)r0 * ldc + col] = v0;
            *(float2*)&C[(long long)(r0 + 8) * ldc + col] = v1;
        }
    }
}

// ---------------------------------------------------------------------------
// Transpose V: vt[(b*NH+h)*DH + d][s] = v[(b*SS+s)*HD + h*DH + d]
// ---------------------------------------------------------------------------
__global__ void transpose_v(const float* __restrict__ v, float* __restrict__ vt)
{
    __shared__ float t[32][33];
    int z = blockIdx.z;
    int b = z / NH, h = z - b * NH;
    int s0 = blockIdx.y * 32, d0 = blockIdx.x * 32;
    int x = threadIdx.x, y = threadIdx.y;
#pragma unroll
    for (int i = 0; i < 32; i += 8)
        t[y + i][x] = v[((long long)(b * SS + s0 + y + i)) * HD + h * DH + d0 + x];
    __syncthreads();
#pragma unroll
    for (int i = 0; i < 32; i += 8)
        vt[((long long)(z * DH + d0 + y + i)) * SS + s0 + x] = t[x][y + i];
}

// ---------------------------------------------------------------------------
// RoPE in-place on a [B*S, H*DH] buffer.
// ---------------------------------------------------------------------------
__global__ void rope_kernel(float* __restrict__ t,
                            const float* __restrict__ fc,
                            const float* __restrict__ fs)
{
    long long idx = (long long)blockIdx.x * blockDim.x + threadIdx.x;
    const long long total = (long long)MR * NH * (DH / 2);
    if (idx >= total) return;
    int i = (int)(idx & 63);
    long long t2 = idx >> 6;
    int h = (int)(t2 % NH);
    long long row = t2 / NH;
    int s = (int)(row % SS);
    float c  = fc[s * 64 + i];
    float sn = fs[s * 64 + i];
    float* p = t + row * HD + h * DH + 2 * i;
    float e = p[0], o = p[1];
    p[0] = e * c - o * sn;
    p[1] = e * sn + o * c;
}

// ---------------------------------------------------------------------------
// Register-resident row softmax: row length 2048, 256 threads, 8 vals/thread.
// One global read + one global write.
// ---------------------------------------------------------------------------
__global__ __launch_bounds__(256) void softmax_rows(float* __restrict__ S)
{
    float* p = S + (long long)blockIdx.x * SS;
    const int t = threadIdx.x;
    __shared__ float red[8];

    float v[8];
#pragma unroll
    for (int j = 0; j < 8; ++j) v[j] = p[t + 256 * j];

    float m = v[0];
#pragma unroll
    for (int j = 1; j < 8; ++j) m = fmaxf(m, v[j]);
#pragma unroll
    for (int o = 16; o > 0; o >>= 1) m = fmaxf(m, __shfl_xor_sync(~0u, m, o));
    if ((t & 31) == 0) red[t >> 5] = m;
    __syncthreads();
    if (t < 32) {
        float mm = red[t & 7];
#pragma unroll
        for (int o = 4; o > 0; o >>= 1) mm = fmaxf(mm, __shfl_xor_sync(~0u, mm, o));
        if (t == 0) red[0] = mm;
    }
    __syncthreads();
    m = red[0];
    __syncthreads();

    float sum = 0.f;
#pragma unroll
    for (int j = 0; j < 8; ++j) { v[j] = __expf(v[j] - m); sum += v[j]; }
#pragma unroll
    for (int o = 16; o > 0; o >>= 1) sum += __shfl_xor_sync(~0u, sum, o);
    if ((t & 31) == 0) red[t >> 5] = sum;
    __syncthreads();
    if (t < 32) {
        float ss = red[t & 7];
#pragma unroll
        for (int o = 4; o > 0; o >>= 1) ss += __shfl_xor_sync(~0u, ss, o);
        if (t == 0) red[0] = ss;
    }
    __syncthreads();
    const float inv = 1.0f / red[0];
#pragma unroll
    for (int j = 0; j < 8; ++j) p[t + 256 * j] = v[j] * inv;
}

// ---------------------------------------------------------------------------

extern "C" void kernel_launch(void* const* d_in, const int* in_sizes, int n_in,
                              void* d_out, int out_size)
{
    const float* x    = (const float*)d_in[0];
    const float* fc   = (const float*)d_in[1];
    const float* fs   = (const float*)d_in[2];
    const float* w_lq = (const float*)d_in[3];
    const float* w_lkv= (const float*)d_in[4];
    const float* w_q  = (const float*)d_in[5];
    const float* w_k  = (const float*)d_in[6];
    const float* w_v  = (const float*)d_in[7];
    const float* w_qr = (const float*)d_in[8];
    const float* b_qr = (const float*)d_in[9];
    const float* w_kr = (const float*)d_in[10];
    const float* b_kr = (const float*)d_in[11];
    const float* w_o  = (const float*)d_in[12];
    const float* b_o  = (const float*)d_in[13];
    float* out = (float*)d_out;

    float *cq, *ckv, *qa, *qr, *ka, *kr, *vv, *vt, *att, *sc;
    cudaGetSymbolAddress((void**)&cq,  g_cq);
    cudaGetSymbolAddress((void**)&ckv, g_ckv);
    cudaGetSymbolAddress((void**)&qa,  g_qa);
    cudaGetSymbolAddress((void**)&qr,  g_qr);
    cudaGetSymbolAddress((void**)&ka,  g_ka);
    cudaGetSymbolAddress((void**)&kr,  g_kr);
    cudaGetSymbolAddress((void**)&vv,  g_v);
    cudaGetSymbolAddress((void**)&vt,  g_vt);
    cudaGetSymbolAddress((void**)&att, g_att);
    cudaGetSymbolAddress((void**)&sc,  g_sc);

    cudaFuncSetAttribute(tgemm<false, false>, cudaFuncAttributeMaxDynamicSharedMemorySize, SMEMSZ);
    cudaFuncSetAttribute(tgemm<true,  false>, cudaFuncAttributeMaxDynamicSharedMemorySize, SMEMSZ);
    cudaFuncSetAttribute(tgemm<false, true >, cudaFuncAttributeMaxDynamicSharedMemorySize, SMEMSZ);

    const float scale = 0.08838834764831845f; // 1/sqrt(128)

    // --- projections (all A[M,K] * B[N,K]^T) ---
    tgemm<false, false><<<dim3(LQ/128, MR/128, 1), 512, SMEMSZ>>>(
        DIM, x, DIM, 0, 0, w_lq, DIM, 0, 0, nullptr, nullptr,
        cq, LQ, 0, 0, nullptr, 1.f, 1);
    tgemm<false, false><<<dim3(LKV/128, MR/128, 1), 512, SMEMSZ>>>(
        DIM, x, DIM, 0, 0, w_lkv, DIM, 0, 0, nullptr, nullptr,
        ckv, LKV, 0, 0, nullptr, 1.f, 1);
    tgemm<false, false><<<dim3(HD/128, MR/128, 1), 512, SMEMSZ>>>(
        LQ, cq, LQ, 0, 0, w_q, LQ, 0, 0, nullptr, nullptr,
        qa, HD, 0, 0, nullptr, 1.f, 1);
    tgemm<true, false><<<dim3(HD/128, MR/128, 1), 512, SMEMSZ>>>(
        LQ, cq, LQ, 0, 0, w_qr, LQ, 0, 0, nullptr, nullptr,
        qr, HD, 0, 0, b_qr, 1.f, 1);
    tgemm<false, false><<<dim3(HD/128, MR/128, 1), 512, SMEMSZ>>>(
        LKV, ckv, LKV, 0, 0, w_k, LKV, 0, 0, nullptr, nullptr,
        ka, HD, 0, 0, nullptr, 1.f, 1);
    tgemm<true, false><<<dim3(HD/128, MR/128, 1), 512, SMEMSZ>>>(
        DIM, x, DIM, 0, 0, w_kr, DIM, 0, 0, nullptr, nullptr,
        kr, HD, 0, 0, b_kr, 1.f, 1);
    tgemm<false, false><<<dim3(HD/128, MR/128, 1), 512, SMEMSZ>>>(
        LKV, ckv, LKV, 0, 0, w_v, LKV, 0, 0, nullptr, nullptr,
        vv, HD, 0, 0, nullptr, 1.f, 1);

    // --- RoPE on qr, kr ---
    {
        long long pairs = (long long)MR * NH * (DH / 2);
        int blocks = (int)((pairs + 255) / 256);
        rope_kernel<<<blocks, 256>>>(qr, fc, fs);
        rope_kernel<<<blocks, 256>>>(kr, fc, fs);
    }

    // --- transpose V for PV GEMM ---
    transpose_v<<<dim3(DH/32, SS/32, BB*NH), dim3(32, 8)>>>(vv, vt);

    // --- scores: sc[z] = (qa.ka^T + qr.kr^T) * scale  (DUAL accumulation) ---
    {
        long long sQb = (long long)SS * HD;
        long long sQh = DH;
        long long sSb = (long long)NH * SS * SS;
        long long sSh = (long long)SS * SS;
        tgemm<false, true><<<dim3(SS/128, SS/128, BB*NH), 512, SMEMSZ>>>(
            DH, qa, HD, sQb, sQh, ka, HD, sQb, sQh, qr, kr,
            sc, SS, sSb, sSh, nullptr, scale, NH);
    }

    // --- softmax (register-resident, one read + one write) ---
    softmax_rows<<<BB * NH * SS, 256>>>(sc);

    // --- PV: att[q, h*DH+d] = P[z] @ vt[z]^T ---
    {
        long long sSb = (long long)NH * SS * SS;
        long long sSh = (long long)SS * SS;
        long long sVtb = (long long)NH * DH * SS;
        long long sVth = (long long)DH * SS;
        long long sCb = (long long)SS * HD;
        long long sCh = DH;
        tgemm<false, false><<<dim3(DH/128, SS/128, BB*NH), 512, SMEMSZ>>>(
            SS, sc, SS, sSb, sSh, vt, SS, sVtb, sVth, nullptr, nullptr,
            att, HD, sCb, sCh, nullptr, 1.f, NH);
    }

    // --- out = att @ w_o^T + b_o ---
    tgemm<true, false><<<dim3(DIM/128, MR/128, 1), 512, SMEMSZ>>>(
        HD, att, HD, 0, 0, w_o, HD, 0, 0, nullptr, nullptr,
        out, DIM, 0, 0, b_o, 1.f, 1);

    (void)in_sizes; (void)n_in; (void)out_size;
}